// round 15
// baseline (speedup 1.0000x reference)
#include <cuda_runtime.h>
#include <math.h>

#define BS 64
#define NUM_CAMS 6
#define NJ 20
#define NPIX 4096          // 64*64
#define NMAPS (BS*NUM_CAMS*NJ)   // 7680
#define K1_BLOCKS 888      // 6 per SM x 148 SMs: persistent grid-stride

// Output layout (tuple order, flattened):
//   kp_3d : (BS, NJ, 3)            -> 3840
//   res   : (BS, NJ)               -> 1280
//   kpc   : (BS, NUM_CAMS, NJ, 3)  -> 23040
//   kph   : (BS, NUM_CAMS, NJ, 3)  -> 23040
#define OFF_KP3D 0
#define OFF_RES  (BS*NJ*3)                     // 3840
#define OFF_KPC  (OFF_RES + BS*NJ)             // 5120
#define OFF_KPH  (OFF_KPC + BS*NUM_CAMS*NJ*3)  // 28160

// ---------------------------------------------------------------------------
// Kernel 1: per-(cam-batch, joint) soft-argmax over 64x64 heatmap.
// PERSISTENT grid-stride blocks (no wave transitions); per-map body is the
// R13-proven code (per-value warp ballots skip the exp work).
// ---------------------------------------------------------------------------
__global__ __launch_bounds__(256)
void softargmax_kernel(const float* __restrict__ hm, float* __restrict__ out)
{
    __shared__ float smax[8];
    __shared__ float sacc[3][8];

    const int t    = threadIdx.x;
    const int wid  = t >> 5;
    const int lane = t & 31;

    for (int map = blockIdx.x; map < NMAPS; map += K1_BLOCKS) {
        const float* p = hm + (size_t)map * NPIX;

        float vals[16];
        float lmax = -1e30f;
#pragma unroll
        for (int i = 0; i < 4; i++) {
            float4 v = __ldcs(reinterpret_cast<const float4*>(p) + i * 256 + t);
            vals[i*4+0] = v.x * 100.0f;
            vals[i*4+1] = v.y * 100.0f;
            vals[i*4+2] = v.z * 100.0f;
            vals[i*4+3] = v.w * 100.0f;
            lmax = fmaxf(lmax, fmaxf(fmaxf(vals[i*4+0], vals[i*4+1]),
                                     fmaxf(vals[i*4+2], vals[i*4+3])));
        }

#pragma unroll
        for (int o = 16; o > 0; o >>= 1)
            lmax = fmaxf(lmax, __shfl_xor_sync(0xffffffffu, lmax, o));
        if (lane == 0) smax[wid] = lmax;
        __syncthreads();
        float m;
        {
            float v0 = smax[0];
#pragma unroll
            for (int w = 1; w < 8; w++) v0 = fmaxf(v0, smax[w]);
            m = v0;
        }

        // exp + weighted sums. expf(x) == 0 exactly for x < ~-104, so
        // skipping those terms matches the reference bit-for-bit.
        float s = 0.f, sx = 0.f, sy = 0.f;
#pragma unroll
        for (int i = 0; i < 4; i++) {
#pragma unroll
            for (int u = 0; u < 4; u++) {
                float d = vals[i*4+u] - m;
                // warp-uniform skip: most warps have no surviving lane
                if (__ballot_sync(0xffffffffu, d > -104.0f)) {
                    if (d > -104.0f) {
                        float e = expf(d);
                        int idx = i * 1024 + t * 4 + u;   // linear pixel index
                        s  += e;
                        sx += e * (float)(idx & 63);      // column (x)
                        sy += e * (float)(idx >> 6);      // row (y)
                    }
                }
            }
        }

#pragma unroll
        for (int o = 16; o > 0; o >>= 1) {
            s  += __shfl_xor_sync(0xffffffffu, s,  o);
            sx += __shfl_xor_sync(0xffffffffu, sx, o);
            sy += __shfl_xor_sync(0xffffffffu, sy, o);
        }
        if (lane == 0) { sacc[0][wid] = s; sacc[1][wid] = sx; sacc[2][wid] = sy; }
        __syncthreads();

        if (t == 0) {
            float S = 0.f, X = 0.f, Y = 0.f;
#pragma unroll
            for (int w = 0; w < 8; w++) { S += sacc[0][w]; X += sacc[1][w]; Y += sacc[2][w]; }
            float recS = 1.0f / S;    // == max(softmax) (peak term is exp(0)=1)
            float x = X * recS;
            float y = Y * recS;
            float* kph = out + OFF_KPH + map * 3;
            float* kpc = out + OFF_KPC + map * 3;
            kph[0] = x;        kph[1] = y;        kph[2] = recS;
            kpc[0] = x * 4.0f; kpc[1] = y * 4.0f; kpc[2] = recS;   // 256/64 = 4
        }
        // No extra barrier needed across iterations:
        //  - smax(k+1) writes happen after sync2(k) (all threads passed it)
        //    and smax(k) reads completed before sync2(k).
        //  - sacc(k+1) writes happen after sync1(k+1), which thread 0 only
        //    reaches after finishing its sacc(k) reads.
    }
}

// ---------------------------------------------------------------------------
// fp64 helpers (float-seeded Newton; operands guaranteed float-range by callers)
// ---------------------------------------------------------------------------
__device__ __forceinline__ double fast_drcp(double d)        // ~2^-48 rel
{
    double r = (double)__frcp_rn((float)d);
    r = r * (2.0 - d * r);
    return r;
}

__device__ __forceinline__ double fast_drsqrt(double d)      // ~2^-46 rel
{
    double r = (double)__frsqrt_rn((float)d);
    r = r * (1.5 - 0.5 * d * r * r);
    return r;
}

// exact power-of-two ~ 1/sqrt(d): zero rounding perturbation, full fp64 range.
__device__ __forceinline__ double pow2_inv_sqrt_approx(double d)
{
    int hi = __double2hiint(d);
    int e  = ((hi >> 20) & 0x7ff) - 1023;   // floor(log2 d)
    int k  = -(e >> 1);                     // ~ -e/2 (within 1)
    return __hiloint2double((1023 + k) << 20, 0);
}

// ---------------------------------------------------------------------------
// Paired Jacobi rotations in commuting (disjoint) planes (R11-R13 proven).
// V is LANE-DISTRIBUTED: each lane owns one eigenvector ROW.
// ---------------------------------------------------------------------------
template<int P, int Q, int R, int S>
__device__ __forceinline__ void jrot_pair(float M[4][4], float Vrow[4])
{
    float apq = M[P][Q],            ars = M[R][S];
    float u1  = M[Q][Q] - M[P][P],  u2  = M[S][S] - M[R][R];
    float w1  = 2.0f * apq,         w2  = 2.0f * ars;
    float z1  = fmaf(u1, u1, w1*w1), z2 = fmaf(u2, u2, w2*w2);
    bool  g1  = (z1 > 1e-30f),      g2  = (z2 > 1e-30f);

    float ir1 = rsqrtf(z1),         ir2 = rsqrtf(z2);      // 1/rho
    float hr1 = 0.5f * ir1,         hr2 = 0.5f * ir2;      // 1/(2 rho)
    float rho1 = z1 * ir1,          rho2 = z2 * ir2;       // rho
    float c2a = (fabsf(u1) + rho1) * hr1;                  // c^2 in [0.5,1]
    float c2b = (fabsf(u2) + rho2) * hr2;
    float ica = rsqrtf(c2a),        icb = rsqrtf(c2b);     // 1/c
    float ca  = c2a * ica,          cb  = c2b * icb;       // c
    float sa  = ((u1 >= 0.0f) ? w1 : -w1) * hr1 * ica;     // s
    float sb  = ((u2 >= 0.0f) ? w2 : -w2) * hr2 * icb;
    float taa = sa * ica,           tbb = sb * icb;        // t = s/c

    float c1 = g1 ? ca  : 1.0f,  s1 = g1 ? sa : 0.0f,  t1 = g1 ? taa : 0.0f;
    float c2 = g2 ? cb  : 1.0f,  s2 = g2 ? sb : 0.0f,  t2 = g2 ? tbb : 0.0f;

    M[P][P] = fmaf(-t1, apq, M[P][P]);
    M[Q][Q] = fmaf( t1, apq, M[Q][Q]);
    M[R][R] = fmaf(-t2, ars, M[R][R]);
    M[S][S] = fmaf( t2, ars, M[S][S]);
    M[P][Q] = 0.0f; M[Q][P] = 0.0f;
    M[R][S] = 0.0f; M[S][R] = 0.0f;

    float bpr = M[P][R], bps = M[P][S], bqr = M[Q][R], bqs = M[Q][S];
    float upr = c1 * bpr - s1 * bqr;
    float uqr = s1 * bpr + c1 * bqr;
    float ups = c1 * bps - s1 * bqs;
    float uqs = s1 * bps + c1 * bqs;
    float npr = c2 * upr - s2 * ups;
    float nps = s2 * upr + c2 * ups;
    float nqr = c2 * uqr - s2 * uqs;
    float nqs = s2 * uqr + c2 * uqs;
    M[P][R] = npr; M[R][P] = npr;  M[P][S] = nps; M[S][P] = nps;
    M[Q][R] = nqr; M[R][Q] = nqr;  M[Q][S] = nqs; M[S][Q] = nqs;

    float vp = Vrow[P], vq = Vrow[Q];
    Vrow[P] = c1 * vp - s1 * vq;
    Vrow[Q] = s1 * vp + c1 * vq;
    float vr = Vrow[R], vs = Vrow[S];
    Vrow[R] = c2 * vr - s2 * vs;
    Vrow[S] = s2 * vr + c2 * vs;
}

// ---------------------------------------------------------------------------
// Kernel 2: DLT triangulation, 4 LANES PER JOINT (8 joints per warp).
// (byte-identical to R13 -- proven 12.9us, rel_err 9.438e-4)
// ---------------------------------------------------------------------------
__global__ __launch_bounds__(32)
void triangulate_kernel(const float* __restrict__ proj,
                        const float* __restrict__ confid,
                        float* __restrict__ out)
{
    const int lane  = threadIdx.x;          // 0..31
    const int quad  = lane >> 2;            // 0..7 : joint within warp
    const int ql    = lane & 3;             // 0..3 : row-group within joint
    const int qbase = lane & ~3;            // first lane of this quad
    const int joint = blockIdx.x * 8 + quad; // 0..1279 (grid=160 exact)
    const int b = joint / NJ;
    const int j = joint % NJ;

    // ---- confidence normalization (replicated; broadcast loads) -----------
    float csum = 0.f;
#pragma unroll
    for (int c = 0; c < NUM_CAMS; c++)
        csum += confid[(b * NUM_CAMS + c) * NJ + j];
    const float rs = 1.0f / csum;

    // ---- this lane's 3 rows of A (rows 3*ql .. 3*ql+2) ---------------------
    const float* kpc = out + OFF_KPC;
    float Af[3][4];
#pragma unroll
    for (int i = 0; i < 3; i++) {
        int n   = 3 * ql + i;
        int cam = n >> 1;
        int par = n & 1;
        const float* Pc = proj + (b * NUM_CAMS + cam) * 12;
        float4 prow = *reinterpret_cast<const float4*>(Pc + par * 4);   // row 0 or 1
        float4 p2   = *reinterpret_cast<const float4*>(Pc + 8);         // row 2
        float  cf   = fmaf(confid[(b * NUM_CAMS + cam) * NJ + j], rs, 1e-5f);
        float  uv   = kpc[((b * NUM_CAMS + cam) * NJ + j) * 3 + par];   // px or py
        Af[i][0] = (p2.x * uv - prow.x) * cf;
        Af[i][1] = (p2.y * uv - prow.y) * cf;
        Af[i][2] = (p2.z * uv - prow.z) * cf;
        Af[i][3] = (p2.w * uv - prow.w) * cf;
    }

    // ---- fp64 M = AtA: per-lane partials over 3 rows, quad butterfly sum ---
    const int PK[10] = {0,0,0,0,1,1,1,2,2,3};
    const int PL[10] = {0,1,2,3,1,2,3,2,3,3};
    double Ad[3][4];
#pragma unroll
    for (int i = 0; i < 3; i++)
#pragma unroll
        for (int k = 0; k < 4; k++) Ad[i][k] = (double)Af[i][k];

    double M[4][4];
#pragma unroll
    for (int e = 0; e < 10; e++) {
        double v = Ad[0][PK[e]] * Ad[0][PL[e]];
        v = fma(Ad[1][PK[e]], Ad[1][PL[e]], v);
        v = fma(Ad[2][PK[e]], Ad[2][PL[e]], v);
        v += __shfl_xor_sync(0xffffffffu, v, 1);
        v += __shfl_xor_sync(0xffffffffu, v, 2);
        M[PK[e]][PL[e]] = v;
        M[PL[e]][PK[e]] = v;
    }

    // ---- fp32 Jacobi: M replicated, V row-distributed (lane ql owns row ql)
    float M32[4][4];
#pragma unroll
    for (int k = 0; k < 4; k++)
#pragma unroll
        for (int l = 0; l < 4; l++) M32[k][l] = (float)M[k][l];

    float Vrow[4] = { (ql == 0) ? 1.0f : 0.0f, (ql == 1) ? 1.0f : 0.0f,
                      (ql == 2) ? 1.0f : 0.0f, (ql == 3) ? 1.0f : 0.0f };

#pragma unroll
    for (int sweep = 0; sweep < 5; sweep++) {
        jrot_pair<0,1,2,3>(M32, Vrow);
        jrot_pair<0,2,1,3>(M32, Vrow);
        jrot_pair<0,3,1,2>(M32, Vrow);
    }

    // seed selection: fp32 diagonal argmin (replicated), gather row components
    int mi = 0; float dmf = M32[0][0];
    if (M32[1][1] < dmf) { dmf = M32[1][1]; mi = 1; }
    if (M32[2][2] < dmf) { dmf = M32[2][2]; mi = 2; }
    if (M32[3][3] < dmf) { dmf = M32[3][3]; mi = 3; }

    float xf = (mi == 0) ? Vrow[0] : (mi == 1) ? Vrow[1]
             : (mi == 2) ? Vrow[2] : Vrow[3];      // this lane's component
    double x0 = (double)__shfl_sync(0xffffffffu, xf, qbase + 0);
    double x1 = (double)__shfl_sync(0xffffffffu, xf, qbase + 1);
    double x2 = (double)__shfl_sync(0xffffffffu, xf, qbase + 2);
    double x3 = (double)__shfl_sync(0xffffffffu, xf, qbase + 3);

    // ---- adjugate of symmetric M: sub-dets + J entries replicated ----------
    double s0 = fma(M[0][0], M[1][1], -M[1][0] * M[0][1]);
    double s1 = fma(M[0][0], M[1][2], -M[1][0] * M[0][2]);
    double s2 = fma(M[0][0], M[1][3], -M[1][0] * M[0][3]);
    double s3 = fma(M[0][1], M[1][2], -M[1][1] * M[0][2]);
    double s4 = fma(M[0][1], M[1][3], -M[1][1] * M[0][3]);
    double s5 = fma(M[0][2], M[1][3], -M[1][2] * M[0][3]);
    double c5 = fma(M[2][2], M[3][3], -M[3][2] * M[2][3]);
    double c4 = fma(M[2][1], M[3][3], -M[3][1] * M[2][3]);
    double c3 = fma(M[2][1], M[3][2], -M[3][1] * M[2][2]);
    double c2 = fma(M[2][0], M[3][3], -M[3][0] * M[2][3]);
    double c1 = fma(M[2][0], M[3][2], -M[3][0] * M[2][2]);

    double J00 = fma( M[1][1], c5, fma(-M[1][2], c4,  M[1][3] * c3));
    double J01 = fma(-M[0][1], c5, fma( M[0][2], c4, -M[0][3] * c3));
    double J02 = fma( M[3][1], s5, fma(-M[3][2], s4,  M[3][3] * s3));
    double J03 = fma(-M[2][1], s5, fma( M[2][2], s4, -M[2][3] * s3));
    double J11 = fma( M[0][0], c5, fma(-M[0][2], c2,  M[0][3] * c1));
    double J12 = fma(-M[3][0], s5, fma( M[3][2], s2, -M[3][3] * s1));
    double J13 = fma( M[2][0], s5, fma(-M[2][2], s2,  M[2][3] * s1));
    double J22 = fma( M[3][0], s4, fma(-M[3][1], s2,  M[3][3] * s0));
    double J23 = fma(-M[2][0], s4, fma( M[2][1], s2, -M[2][3] * s0));
    double J33 = fma( M[2][0], s3, fma(-M[2][1], s1,  M[2][2] * s0));

    // this lane's J row (cheap ALU selects; J symmetric)
    double Jr0 = (ql == 0) ? J00 : (ql == 1) ? J01 : (ql == 2) ? J02 : J03;
    double Jr1 = (ql == 0) ? J01 : (ql == 1) ? J11 : (ql == 2) ? J12 : J13;
    double Jr2 = (ql == 0) ? J02 : (ql == 1) ? J12 : (ql == 2) ? J22 : J23;
    double Jr3 = (ql == 0) ? J03 : (ql == 1) ? J13 : (ql == 2) ? J23 : J33;

    // two adjugate applications, ROW-DISTRIBUTED (1 component per lane)
    double yl = fma(Jr0, x0, fma(Jr1, x1, fma(Jr2, x2, Jr3 * x3)));
    double y0 = __shfl_sync(0xffffffffu, yl, qbase + 0);
    double y1 = __shfl_sync(0xffffffffu, yl, qbase + 1);
    double y2 = __shfl_sync(0xffffffffu, yl, qbase + 2);
    double y3 = __shfl_sync(0xffffffffu, yl, qbase + 3);
    double xl = fma(Jr0, y0, fma(Jr1, y1, fma(Jr2, y2, Jr3 * y3)));
    x0 = __shfl_sync(0xffffffffu, xl, qbase + 0);
    x1 = __shfl_sync(0xffffffffu, xl, qbase + 1);
    x2 = __shfl_sync(0xffffffffu, xl, qbase + 2);
    x3 = __shfl_sync(0xffffffffu, xl, qbase + 3);

    // exact pow2 renorm; nrm2 of scaled vector is (n2*sc)*sc EXACTLY
    double n2 = fma(x0, x0, fma(x1, x1, fma(x2, x2, x3 * x3)));
    double sc = pow2_inv_sqrt_approx(n2);
    x0 *= sc; x1 *= sc; x2 *= sc; x3 *= sc;
    double nrm2 = (n2 * sc) * sc;               // in ~[0.25, 4]

    // kp_3d = x[:3]/x[3]  (normalization- and sign-invariant); lane 0 of quad
    if (ql == 0) {
        double inv = fast_drcp(x3);
        float* kp3 = out + OFF_KP3D + joint * 3;
        kp3[0] = (float)(x0 * inv);
        kp3[1] = (float)(x1 * inv);
        kp3[2] = (float)(x2 * inv);
    }

    // res = (sum_n |A[n,:].x|) / ||x|| -- rows distributed, quad-reduced
    double acc = 0.0;
#pragma unroll
    for (int i = 0; i < 3; i++) {
        double dsum = fma(Ad[i][0], x0, fma(Ad[i][1], x1,
                      fma(Ad[i][2], x2, Ad[i][3] * x3)));
        acc += fabs(dsum);
    }
    acc += __shfl_xor_sync(0xffffffffu, acc, 1);
    acc += __shfl_xor_sync(0xffffffffu, acc, 2);
    if (ql == 0)
        out[OFF_RES + joint] = (float)(acc * fast_drsqrt(nrm2));
}

// ---------------------------------------------------------------------------
extern "C" void kernel_launch(void* const* d_in, const int* in_sizes, int n_in,
                              void* d_out, int out_size)
{
    const float* heatmap = (const float*)d_in[0];  // (384, 20, 64, 64)
    const float* proj    = (const float*)d_in[1];  // (64, 6, 3, 4)
    const float* confid  = (const float*)d_in[2];  // (384, 20)
    float* out = (float*)d_out;                    // 51200 floats

    softargmax_kernel<<<K1_BLOCKS, 256>>>(heatmap, out);
    triangulate_kernel<<<160, 32>>>(proj, confid, out);   // 160*8 = 1280 joints
}

// round 16
// speedup vs baseline: 1.3551x; 1.3551x over previous
#include <cuda_runtime.h>
#include <math.h>

#define BS 64
#define NUM_CAMS 6
#define NJ 20
#define NPIX 4096          // 64*64
#define NMAPS (BS*NUM_CAMS*NJ)   // 7680

// Output layout (tuple order, flattened):
//   kp_3d : (BS, NJ, 3)            -> 3840
//   res   : (BS, NJ)               -> 1280
//   kpc   : (BS, NUM_CAMS, NJ, 3)  -> 23040
//   kph   : (BS, NUM_CAMS, NJ, 3)  -> 23040
#define OFF_KP3D 0
#define OFF_RES  (BS*NJ*3)                     // 3840
#define OFF_KPC  (OFF_RES + BS*NJ)             // 5120
#define OFF_KPH  (OFF_KPC + BS*NUM_CAMS*NJ*3)  // 28160

// ---------------------------------------------------------------------------
// Kernel 1: per-(cam-batch, joint) soft-argmax over 64x64 heatmap.
// One block per map (R13-proven structure). Ballot count reduced 16 -> 4 by
// gating on each 4-value chunk's max; the per-value predicate inside a
// surviving chunk is kept, so executed arithmetic is identical to R13.
// ---------------------------------------------------------------------------
__global__ __launch_bounds__(256)
void softargmax_kernel(const float* __restrict__ hm, float* __restrict__ out)
{
    const int map = blockIdx.x;                 // 0..7679
    const float* p = hm + (size_t)map * NPIX;
    const int t = threadIdx.x;

    float vals[16];
    float cmax[4];
    float lmax = -1e30f;
#pragma unroll
    for (int i = 0; i < 4; i++) {
        float4 v = __ldcs(reinterpret_cast<const float4*>(p) + i * 256 + t);
        vals[i*4+0] = v.x * 100.0f;
        vals[i*4+1] = v.y * 100.0f;
        vals[i*4+2] = v.z * 100.0f;
        vals[i*4+3] = v.w * 100.0f;
        cmax[i] = fmaxf(fmaxf(vals[i*4+0], vals[i*4+1]),
                        fmaxf(vals[i*4+2], vals[i*4+3]));
        lmax = fmaxf(lmax, cmax[i]);
    }

    __shared__ float smax[8];
    __shared__ float sacc[3][8];

    const int wid  = t >> 5;
    const int lane = t & 31;

#pragma unroll
    for (int o = 16; o > 0; o >>= 1)
        lmax = fmaxf(lmax, __shfl_xor_sync(0xffffffffu, lmax, o));
    if (lane == 0) smax[wid] = lmax;
    __syncthreads();
    float m;
    {
        float v0 = smax[0];
#pragma unroll
        for (int w = 1; w < 8; w++) v0 = fmaxf(v0, smax[w]);
        m = v0;
    }

    // exp + weighted sums. expf(x) == 0 exactly for x < ~-104, so skipping
    // those terms matches the reference bit-for-bit (mod summation order).
    // Gate per 4-value chunk (1 ballot) instead of per value (4 ballots);
    // inside a surviving chunk keep the per-value predicate (same work as R13).
    float s = 0.f, sx = 0.f, sy = 0.f;
#pragma unroll
    for (int i = 0; i < 4; i++) {
        if (__ballot_sync(0xffffffffu, cmax[i] - m > -104.0f)) {
#pragma unroll
            for (int u = 0; u < 4; u++) {
                float d = vals[i*4+u] - m;
                if (d > -104.0f) {
                    float e = expf(d);
                    int idx = i * 1024 + t * 4 + u;   // linear pixel index
                    s  += e;
                    sx += e * (float)(idx & 63);      // column (x)
                    sy += e * (float)(idx >> 6);      // row (y)
                }
            }
        }
    }

#pragma unroll
    for (int o = 16; o > 0; o >>= 1) {
        s  += __shfl_xor_sync(0xffffffffu, s,  o);
        sx += __shfl_xor_sync(0xffffffffu, sx, o);
        sy += __shfl_xor_sync(0xffffffffu, sy, o);
    }
    if (lane == 0) { sacc[0][wid] = s; sacc[1][wid] = sx; sacc[2][wid] = sy; }
    __syncthreads();

    if (t == 0) {
        float S = 0.f, X = 0.f, Y = 0.f;
#pragma unroll
        for (int w = 0; w < 8; w++) { S += sacc[0][w]; X += sacc[1][w]; Y += sacc[2][w]; }
        float recS = 1.0f / S;        // == max(softmax) (peak term is exp(0)=1)
        float x = X * recS;
        float y = Y * recS;
        float* kph = out + OFF_KPH + map * 3;
        float* kpc = out + OFF_KPC + map * 3;
        kph[0] = x;        kph[1] = y;        kph[2] = recS;
        kpc[0] = x * 4.0f; kpc[1] = y * 4.0f; kpc[2] = recS;   // 256/64 = 4
    }
}

// ---------------------------------------------------------------------------
// fp64 helpers (float-seeded Newton; operands guaranteed float-range by callers)
// ---------------------------------------------------------------------------
__device__ __forceinline__ double fast_drcp(double d)        // ~2^-48 rel
{
    double r = (double)__frcp_rn((float)d);
    r = r * (2.0 - d * r);
    return r;
}

__device__ __forceinline__ double fast_drsqrt(double d)      // ~2^-46 rel
{
    double r = (double)__frsqrt_rn((float)d);
    r = r * (1.5 - 0.5 * d * r * r);
    return r;
}

// exact power-of-two ~ 1/sqrt(d): zero rounding perturbation, full fp64 range.
__device__ __forceinline__ double pow2_inv_sqrt_approx(double d)
{
    int hi = __double2hiint(d);
    int e  = ((hi >> 20) & 0x7ff) - 1023;   // floor(log2 d)
    int k  = -(e >> 1);                     // ~ -e/2 (within 1)
    return __hiloint2double((1023 + k) << 20, 0);
}

// ---------------------------------------------------------------------------
// Paired Jacobi rotations in commuting (disjoint) planes (R11-R13 proven).
// V is LANE-DISTRIBUTED: each lane owns one eigenvector ROW.
// ---------------------------------------------------------------------------
template<int P, int Q, int R, int S>
__device__ __forceinline__ void jrot_pair(float M[4][4], float Vrow[4])
{
    float apq = M[P][Q],            ars = M[R][S];
    float u1  = M[Q][Q] - M[P][P],  u2  = M[S][S] - M[R][R];
    float w1  = 2.0f * apq,         w2  = 2.0f * ars;
    float z1  = fmaf(u1, u1, w1*w1), z2 = fmaf(u2, u2, w2*w2);
    bool  g1  = (z1 > 1e-30f),      g2  = (z2 > 1e-30f);

    float ir1 = rsqrtf(z1),         ir2 = rsqrtf(z2);      // 1/rho
    float hr1 = 0.5f * ir1,         hr2 = 0.5f * ir2;      // 1/(2 rho)
    float rho1 = z1 * ir1,          rho2 = z2 * ir2;       // rho
    float c2a = (fabsf(u1) + rho1) * hr1;                  // c^2 in [0.5,1]
    float c2b = (fabsf(u2) + rho2) * hr2;
    float ica = rsqrtf(c2a),        icb = rsqrtf(c2b);     // 1/c
    float ca  = c2a * ica,          cb  = c2b * icb;       // c
    float sa  = ((u1 >= 0.0f) ? w1 : -w1) * hr1 * ica;     // s
    float sb  = ((u2 >= 0.0f) ? w2 : -w2) * hr2 * icb;
    float taa = sa * ica,           tbb = sb * icb;        // t = s/c

    float c1 = g1 ? ca  : 1.0f,  s1 = g1 ? sa : 0.0f,  t1 = g1 ? taa : 0.0f;
    float c2 = g2 ? cb  : 1.0f,  s2 = g2 ? sb : 0.0f,  t2 = g2 ? tbb : 0.0f;

    M[P][P] = fmaf(-t1, apq, M[P][P]);
    M[Q][Q] = fmaf( t1, apq, M[Q][Q]);
    M[R][R] = fmaf(-t2, ars, M[R][R]);
    M[S][S] = fmaf( t2, ars, M[S][S]);
    M[P][Q] = 0.0f; M[Q][P] = 0.0f;
    M[R][S] = 0.0f; M[S][R] = 0.0f;

    float bpr = M[P][R], bps = M[P][S], bqr = M[Q][R], bqs = M[Q][S];
    float upr = c1 * bpr - s1 * bqr;
    float uqr = s1 * bpr + c1 * bqr;
    float ups = c1 * bps - s1 * bqs;
    float uqs = s1 * bps + c1 * bqs;
    float npr = c2 * upr - s2 * ups;
    float nps = s2 * upr + c2 * ups;
    float nqr = c2 * uqr - s2 * uqs;
    float nqs = s2 * uqr + c2 * uqs;
    M[P][R] = npr; M[R][P] = npr;  M[P][S] = nps; M[S][P] = nps;
    M[Q][R] = nqr; M[R][Q] = nqr;  M[Q][S] = nqs; M[S][Q] = nqs;

    float vp = Vrow[P], vq = Vrow[Q];
    Vrow[P] = c1 * vp - s1 * vq;
    Vrow[Q] = s1 * vp + c1 * vq;
    float vr = Vrow[R], vs = Vrow[S];
    Vrow[R] = c2 * vr - s2 * vs;
    Vrow[S] = s2 * vr + c2 * vs;
}

// ---------------------------------------------------------------------------
// Kernel 2: DLT triangulation, 4 LANES PER JOINT (8 joints per warp).
// (byte-identical to R13 -- proven 12.9us, rel_err 9.438e-4)
// ---------------------------------------------------------------------------
__global__ __launch_bounds__(32)
void triangulate_kernel(const float* __restrict__ proj,
                        const float* __restrict__ confid,
                        float* __restrict__ out)
{
    const int lane  = threadIdx.x;          // 0..31
    const int quad  = lane >> 2;            // 0..7 : joint within warp
    const int ql    = lane & 3;             // 0..3 : row-group within joint
    const int qbase = lane & ~3;            // first lane of this quad
    const int joint = blockIdx.x * 8 + quad; // 0..1279 (grid=160 exact)
    const int b = joint / NJ;
    const int j = joint % NJ;

    // ---- confidence normalization (replicated; broadcast loads) -----------
    float csum = 0.f;
#pragma unroll
    for (int c = 0; c < NUM_CAMS; c++)
        csum += confid[(b * NUM_CAMS + c) * NJ + j];
    const float rs = 1.0f / csum;

    // ---- this lane's 3 rows of A (rows 3*ql .. 3*ql+2) ---------------------
    const float* kpc = out + OFF_KPC;
    float Af[3][4];
#pragma unroll
    for (int i = 0; i < 3; i++) {
        int n   = 3 * ql + i;
        int cam = n >> 1;
        int par = n & 1;
        const float* Pc = proj + (b * NUM_CAMS + cam) * 12;
        float4 prow = *reinterpret_cast<const float4*>(Pc + par * 4);   // row 0 or 1
        float4 p2   = *reinterpret_cast<const float4*>(Pc + 8);         // row 2
        float  cf   = fmaf(confid[(b * NUM_CAMS + cam) * NJ + j], rs, 1e-5f);
        float  uv   = kpc[((b * NUM_CAMS + cam) * NJ + j) * 3 + par];   // px or py
        Af[i][0] = (p2.x * uv - prow.x) * cf;
        Af[i][1] = (p2.y * uv - prow.y) * cf;
        Af[i][2] = (p2.z * uv - prow.z) * cf;
        Af[i][3] = (p2.w * uv - prow.w) * cf;
    }

    // ---- fp64 M = AtA: per-lane partials over 3 rows, quad butterfly sum ---
    const int PK[10] = {0,0,0,0,1,1,1,2,2,3};
    const int PL[10] = {0,1,2,3,1,2,3,2,3,3};
    double Ad[3][4];
#pragma unroll
    for (int i = 0; i < 3; i++)
#pragma unroll
        for (int k = 0; k < 4; k++) Ad[i][k] = (double)Af[i][k];

    double M[4][4];
#pragma unroll
    for (int e = 0; e < 10; e++) {
        double v = Ad[0][PK[e]] * Ad[0][PL[e]];
        v = fma(Ad[1][PK[e]], Ad[1][PL[e]], v);
        v = fma(Ad[2][PK[e]], Ad[2][PL[e]], v);
        v += __shfl_xor_sync(0xffffffffu, v, 1);
        v += __shfl_xor_sync(0xffffffffu, v, 2);
        M[PK[e]][PL[e]] = v;
        M[PL[e]][PK[e]] = v;
    }

    // ---- fp32 Jacobi: M replicated, V row-distributed (lane ql owns row ql)
    float M32[4][4];
#pragma unroll
    for (int k = 0; k < 4; k++)
#pragma unroll
        for (int l = 0; l < 4; l++) M32[k][l] = (float)M[k][l];

    float Vrow[4] = { (ql == 0) ? 1.0f : 0.0f, (ql == 1) ? 1.0f : 0.0f,
                      (ql == 2) ? 1.0f : 0.0f, (ql == 3) ? 1.0f : 0.0f };

#pragma unroll
    for (int sweep = 0; sweep < 5; sweep++) {
        jrot_pair<0,1,2,3>(M32, Vrow);
        jrot_pair<0,2,1,3>(M32, Vrow);
        jrot_pair<0,3,1,2>(M32, Vrow);
    }

    // seed selection: fp32 diagonal argmin (replicated), gather row components
    int mi = 0; float dmf = M32[0][0];
    if (M32[1][1] < dmf) { dmf = M32[1][1]; mi = 1; }
    if (M32[2][2] < dmf) { dmf = M32[2][2]; mi = 2; }
    if (M32[3][3] < dmf) { dmf = M32[3][3]; mi = 3; }

    float xf = (mi == 0) ? Vrow[0] : (mi == 1) ? Vrow[1]
             : (mi == 2) ? Vrow[2] : Vrow[3];      // this lane's component
    double x0 = (double)__shfl_sync(0xffffffffu, xf, qbase + 0);
    double x1 = (double)__shfl_sync(0xffffffffu, xf, qbase + 1);
    double x2 = (double)__shfl_sync(0xffffffffu, xf, qbase + 2);
    double x3 = (double)__shfl_sync(0xffffffffu, xf, qbase + 3);

    // ---- adjugate of symmetric M: sub-dets + J entries replicated ----------
    double s0 = fma(M[0][0], M[1][1], -M[1][0] * M[0][1]);
    double s1 = fma(M[0][0], M[1][2], -M[1][0] * M[0][2]);
    double s2 = fma(M[0][0], M[1][3], -M[1][0] * M[0][3]);
    double s3 = fma(M[0][1], M[1][2], -M[1][1] * M[0][2]);
    double s4 = fma(M[0][1], M[1][3], -M[1][1] * M[0][3]);
    double s5 = fma(M[0][2], M[1][3], -M[1][2] * M[0][3]);
    double c5 = fma(M[2][2], M[3][3], -M[3][2] * M[2][3]);
    double c4 = fma(M[2][1], M[3][3], -M[3][1] * M[2][3]);
    double c3 = fma(M[2][1], M[3][2], -M[3][1] * M[2][2]);
    double c2 = fma(M[2][0], M[3][3], -M[3][0] * M[2][3]);
    double c1 = fma(M[2][0], M[3][2], -M[3][0] * M[2][2]);

    double J00 = fma( M[1][1], c5, fma(-M[1][2], c4,  M[1][3] * c3));
    double J01 = fma(-M[0][1], c5, fma( M[0][2], c4, -M[0][3] * c3));
    double J02 = fma( M[3][1], s5, fma(-M[3][2], s4,  M[3][3] * s3));
    double J03 = fma(-M[2][1], s5, fma( M[2][2], s4, -M[2][3] * s3));
    double J11 = fma( M[0][0], c5, fma(-M[0][2], c2,  M[0][3] * c1));
    double J12 = fma(-M[3][0], s5, fma( M[3][2], s2, -M[3][3] * s1));
    double J13 = fma( M[2][0], s5, fma(-M[2][2], s2,  M[2][3] * s1));
    double J22 = fma( M[3][0], s4, fma(-M[3][1], s2,  M[3][3] * s0));
    double J23 = fma(-M[2][0], s4, fma( M[2][1], s2, -M[2][3] * s0));
    double J33 = fma( M[2][0], s3, fma(-M[2][1], s1,  M[2][2] * s0));

    // this lane's J row (cheap ALU selects; J symmetric)
    double Jr0 = (ql == 0) ? J00 : (ql == 1) ? J01 : (ql == 2) ? J02 : J03;
    double Jr1 = (ql == 0) ? J01 : (ql == 1) ? J11 : (ql == 2) ? J12 : J13;
    double Jr2 = (ql == 0) ? J02 : (ql == 1) ? J12 : (ql == 2) ? J22 : J23;
    double Jr3 = (ql == 0) ? J03 : (ql == 1) ? J13 : (ql == 2) ? J23 : J33;

    // two adjugate applications, ROW-DISTRIBUTED (1 component per lane)
    double yl = fma(Jr0, x0, fma(Jr1, x1, fma(Jr2, x2, Jr3 * x3)));
    double y0 = __shfl_sync(0xffffffffu, yl, qbase + 0);
    double y1 = __shfl_sync(0xffffffffu, yl, qbase + 1);
    double y2 = __shfl_sync(0xffffffffu, yl, qbase + 2);
    double y3 = __shfl_sync(0xffffffffu, yl, qbase + 3);
    double xl = fma(Jr0, y0, fma(Jr1, y1, fma(Jr2, y2, Jr3 * y3)));
    x0 = __shfl_sync(0xffffffffu, xl, qbase + 0);
    x1 = __shfl_sync(0xffffffffu, xl, qbase + 1);
    x2 = __shfl_sync(0xffffffffu, xl, qbase + 2);
    x3 = __shfl_sync(0xffffffffu, xl, qbase + 3);

    // exact pow2 renorm; nrm2 of scaled vector is (n2*sc)*sc EXACTLY
    double n2 = fma(x0, x0, fma(x1, x1, fma(x2, x2, x3 * x3)));
    double sc = pow2_inv_sqrt_approx(n2);
    x0 *= sc; x1 *= sc; x2 *= sc; x3 *= sc;
    double nrm2 = (n2 * sc) * sc;               // in ~[0.25, 4]

    // kp_3d = x[:3]/x[3]  (normalization- and sign-invariant); lane 0 of quad
    if (ql == 0) {
        double inv = fast_drcp(x3);
        float* kp3 = out + OFF_KP3D + joint * 3;
        kp3[0] = (float)(x0 * inv);
        kp3[1] = (float)(x1 * inv);
        kp3[2] = (float)(x2 * inv);
    }

    // res = (sum_n |A[n,:].x|) / ||x|| -- rows distributed, quad-reduced
    double acc = 0.0;
#pragma unroll
    for (int i = 0; i < 3; i++) {
        double dsum = fma(Ad[i][0], x0, fma(Ad[i][1], x1,
                      fma(Ad[i][2], x2, Ad[i][3] * x3)));
        acc += fabs(dsum);
    }
    acc += __shfl_xor_sync(0xffffffffu, acc, 1);
    acc += __shfl_xor_sync(0xffffffffu, acc, 2);
    if (ql == 0)
        out[OFF_RES + joint] = (float)(acc * fast_drsqrt(nrm2));
}

// ---------------------------------------------------------------------------
extern "C" void kernel_launch(void* const* d_in, const int* in_sizes, int n_in,
                              void* d_out, int out_size)
{
    const float* heatmap = (const float*)d_in[0];  // (384, 20, 64, 64)
    const float* proj    = (const float*)d_in[1];  // (64, 6, 3, 4)
    const float* confid  = (const float*)d_in[2];  // (384, 20)
    float* out = (float*)d_out;                    // 51200 floats

    softargmax_kernel<<<NMAPS, 256>>>(heatmap, out);
    triangulate_kernel<<<160, 32>>>(proj, confid, out);   // 160*8 = 1280 joints
}